// round 1
// baseline (speedup 1.0000x reference)
#include <cuda_runtime.h>
#include <math_constants.h>

#define Bsz 8
#define Nseq 1024
#define Cdim 1024
#define Hn 16
#define Dh 64
#define OQKV 3072

// Scratch (allocation-free rule: __device__ globals)
__device__ float g_q[Bsz * Hn * Nseq * Dh];
__device__ float g_k[Bsz * Hn * Nseq * Dh];
__device__ float g_v[Bsz * Hn * Nseq * Dh];
__device__ float g_ao[Bsz * Nseq * Cdim];

// ---------------------------------------------------------------------------
// QKV GEMM: qkv[m, o] = sum_k X[m,k] * Wqkv[o,k]   (m = b*N+n, o in [0,3072))
// 128x128 tile, BK=8, 256 threads, 8x8 per thread. Epilogue scatters into
// g_q/g_k/g_v laid out [B,H,N,D].
// ---------------------------------------------------------------------------
__global__ __launch_bounds__(256) void qkv_gemm(const float* __restrict__ X,
                                                const float* __restrict__ W) {
    const int K = Cdim;
    __shared__ float As[8][128];
    __shared__ float Bs[8][128];
    const int tid   = threadIdx.x;
    const int m0    = blockIdx.y * 128;
    const int o0    = blockIdx.x * 128;
    const int mload = tid >> 1;          // 0..127
    const int kload = (tid & 1) << 2;    // 0 or 4
    const int tr    = tid >> 4;          // 0..15
    const int tc    = tid & 15;          // 0..15

    float acc[8][8];
#pragma unroll
    for (int i = 0; i < 8; i++)
#pragma unroll
        for (int j = 0; j < 8; j++) acc[i][j] = 0.0f;

    for (int k0 = 0; k0 < K; k0 += 8) {
        float4 av = *(const float4*)(X + (m0 + mload) * K + k0 + kload);
        float4 bv = *(const float4*)(W + (o0 + mload) * K + k0 + kload);
        As[kload + 0][mload] = av.x; As[kload + 1][mload] = av.y;
        As[kload + 2][mload] = av.z; As[kload + 3][mload] = av.w;
        Bs[kload + 0][mload] = bv.x; Bs[kload + 1][mload] = bv.y;
        Bs[kload + 2][mload] = bv.z; Bs[kload + 3][mload] = bv.w;
        __syncthreads();
#pragma unroll
        for (int kk = 0; kk < 8; kk++) {
            float a[8], b[8];
            *(float4*)&a[0] = *(const float4*)&As[kk][tr * 8];
            *(float4*)&a[4] = *(const float4*)&As[kk][tr * 8 + 4];
            *(float4*)&b[0] = *(const float4*)&Bs[kk][tc * 8];
            *(float4*)&b[4] = *(const float4*)&Bs[kk][tc * 8 + 4];
#pragma unroll
            for (int i = 0; i < 8; i++)
#pragma unroll
                for (int j = 0; j < 8; j++)
                    acc[i][j] = fmaf(a[i], b[j], acc[i][j]);
        }
        __syncthreads();
    }

    // Epilogue: o in [o0, o0+128). 1024 % 128 == 0 -> whole tile is in exactly
    // one of q/k/v. Each thread's 8 columns are 8-aligned -> same head.
    const int which = o0 >> 10;  // 0=q, 1=k, 2=v
    float* dstbase = (which == 0) ? g_q : (which == 1) ? g_k : g_v;
    const int ocol = o0 + tc * 8;
    const int h    = (ocol & 1023) >> 6;
    const int d0   = ocol & 63;
#pragma unroll
    for (int i = 0; i < 8; i++) {
        int m = m0 + tr * 8 + i;
        int b = m >> 10;
        int n = m & 1023;
        float* dst = dstbase + (((b * Hn + h) * Nseq + n) * Dh + d0);
        float4 v0 = make_float4(acc[i][0], acc[i][1], acc[i][2], acc[i][3]);
        float4 v1 = make_float4(acc[i][4], acc[i][5], acc[i][6], acc[i][7]);
        *(float4*)(dst)     = v0;
        *(float4*)(dst + 4) = v1;
    }
}

// ---------------------------------------------------------------------------
// Flash attention, fp32, exp2 domain. One thread per query row, 128 rows/CTA,
// K/V streamed through smem in 16-row tiles. grid = (B*H, N/128).
// ---------------------------------------------------------------------------
__global__ __launch_bounds__(128) void attn_kernel() {
    const int bh  = blockIdx.x;
    const int row = blockIdx.y * 128 + threadIdx.x;
    const float* Qp = g_q + bh * (Nseq * Dh);
    const float* Kp = g_k + bh * (Nseq * Dh);
    const float* Vp = g_v + bh * (Nseq * Dh);

    __shared__ float4 Ks[16][16];   // 16 rows x 64 floats
    __shared__ float4 Vs[16][16];

    // q scaled by SCALE * log2(e) so logits live in log2 domain
    const float qs = 0.125f * 1.44269504088896340736f;
    float q[64];
#pragma unroll
    for (int d4 = 0; d4 < 16; d4++) {
        float4 t = ((const float4*)(Qp + row * Dh))[d4];
        q[d4 * 4 + 0] = t.x * qs; q[d4 * 4 + 1] = t.y * qs;
        q[d4 * 4 + 2] = t.z * qs; q[d4 * 4 + 3] = t.w * qs;
    }

    float o[64];
#pragma unroll
    for (int d = 0; d < 64; d++) o[d] = 0.0f;
    float mi = -CUDART_INF_F;
    float li = 0.0f;

    for (int j0 = 0; j0 < Nseq; j0 += 16) {
        const float4* ksrc = (const float4*)(Kp + j0 * Dh);
        const float4* vsrc = (const float4*)(Vp + j0 * Dh);
        ((float4*)Ks)[threadIdx.x]       = ksrc[threadIdx.x];
        ((float4*)Ks)[threadIdx.x + 128] = ksrc[threadIdx.x + 128];
        ((float4*)Vs)[threadIdx.x]       = vsrc[threadIdx.x];
        ((float4*)Vs)[threadIdx.x + 128] = vsrc[threadIdx.x + 128];
        __syncthreads();

        float s[16];
        float tmax = -CUDART_INF_F;
#pragma unroll
        for (int r = 0; r < 16; r++) {
            float accv = 0.0f;
#pragma unroll
            for (int d4 = 0; d4 < 16; d4++) {
                float4 kv = Ks[r][d4];
                accv = fmaf(q[d4 * 4 + 0], kv.x, accv);
                accv = fmaf(q[d4 * 4 + 1], kv.y, accv);
                accv = fmaf(q[d4 * 4 + 2], kv.z, accv);
                accv = fmaf(q[d4 * 4 + 3], kv.w, accv);
            }
            s[r] = accv;
            tmax = fmaxf(tmax, accv);
        }

        float mnew  = fmaxf(mi, tmax);
        float alpha = exp2f(mi - mnew);
        li *= alpha;
#pragma unroll
        for (int d = 0; d < 64; d++) o[d] *= alpha;

#pragma unroll
        for (int r = 0; r < 16; r++) {
            float p = exp2f(s[r] - mnew);
            li += p;
#pragma unroll
            for (int d4 = 0; d4 < 16; d4++) {
                float4 vv = Vs[r][d4];
                o[d4 * 4 + 0] = fmaf(p, vv.x, o[d4 * 4 + 0]);
                o[d4 * 4 + 1] = fmaf(p, vv.y, o[d4 * 4 + 1]);
                o[d4 * 4 + 2] = fmaf(p, vv.z, o[d4 * 4 + 2]);
                o[d4 * 4 + 3] = fmaf(p, vv.w, o[d4 * 4 + 3]);
            }
        }
        mi = mnew;
        __syncthreads();
    }

    const float inv = 1.0f / li;
    const int b = bh >> 4;
    const int h = bh & 15;
    float* dst = g_ao + ((b * Nseq + row) * Cdim + h * Dh);
#pragma unroll
    for (int d4 = 0; d4 < 16; d4++) {
        float4 t = make_float4(o[d4 * 4 + 0] * inv, o[d4 * 4 + 1] * inv,
                               o[d4 * 4 + 2] * inv, o[d4 * 4 + 3] * inv);
        ((float4*)dst)[d4] = t;
    }
}

// ---------------------------------------------------------------------------
// Projection GEMM: out[m, o] = sum_k g_ao[m,k] * Wp[o,k] + bias[o]
// ---------------------------------------------------------------------------
__global__ __launch_bounds__(256) void proj_gemm(const float* __restrict__ W,
                                                 const float* __restrict__ bias,
                                                 float* __restrict__ out) {
    const int K = Cdim;
    __shared__ float As[8][128];
    __shared__ float Bs[8][128];
    const int tid   = threadIdx.x;
    const int m0    = blockIdx.y * 128;
    const int o0    = blockIdx.x * 128;
    const int mload = tid >> 1;
    const int kload = (tid & 1) << 2;
    const int tr    = tid >> 4;
    const int tc    = tid & 15;

    float acc[8][8];
#pragma unroll
    for (int i = 0; i < 8; i++)
#pragma unroll
        for (int j = 0; j < 8; j++) acc[i][j] = 0.0f;

    const float* A = g_ao;
    for (int k0 = 0; k0 < K; k0 += 8) {
        float4 av = *(const float4*)(A + (m0 + mload) * K + k0 + kload);
        float4 bv = *(const float4*)(W + (o0 + mload) * K + k0 + kload);
        As[kload + 0][mload] = av.x; As[kload + 1][mload] = av.y;
        As[kload + 2][mload] = av.z; As[kload + 3][mload] = av.w;
        Bs[kload + 0][mload] = bv.x; Bs[kload + 1][mload] = bv.y;
        Bs[kload + 2][mload] = bv.z; Bs[kload + 3][mload] = bv.w;
        __syncthreads();
#pragma unroll
        for (int kk = 0; kk < 8; kk++) {
            float a[8], b[8];
            *(float4*)&a[0] = *(const float4*)&As[kk][tr * 8];
            *(float4*)&a[4] = *(const float4*)&As[kk][tr * 8 + 4];
            *(float4*)&b[0] = *(const float4*)&Bs[kk][tc * 8];
            *(float4*)&b[4] = *(const float4*)&Bs[kk][tc * 8 + 4];
#pragma unroll
            for (int i = 0; i < 8; i++)
#pragma unroll
                for (int j = 0; j < 8; j++)
                    acc[i][j] = fmaf(a[i], b[j], acc[i][j]);
        }
        __syncthreads();
    }

    const int ocol = o0 + tc * 8;
    float4 bias0 = *(const float4*)(bias + ocol);
    float4 bias1 = *(const float4*)(bias + ocol + 4);
#pragma unroll
    for (int i = 0; i < 8; i++) {
        int m = m0 + tr * 8 + i;
        float* dst = out + (m * Cdim + ocol);
        float4 v0 = make_float4(acc[i][0] + bias0.x, acc[i][1] + bias0.y,
                                acc[i][2] + bias0.z, acc[i][3] + bias0.w);
        float4 v1 = make_float4(acc[i][4] + bias1.x, acc[i][5] + bias1.y,
                                acc[i][6] + bias1.z, acc[i][7] + bias1.w);
        *(float4*)(dst)     = v0;
        *(float4*)(dst + 4) = v1;
    }
}

extern "C" void kernel_launch(void* const* d_in, const int* in_sizes, int n_in,
                              void* d_out, int out_size) {
    const float* x      = (const float*)d_in[0];   // [8,1024,1024]
    const float* w_qkv  = (const float*)d_in[1];   // [3072,1024]
    const float* w_proj = (const float*)d_in[2];   // [1024,1024]
    const float* b_proj = (const float*)d_in[3];   // [1024]
    float* out = (float*)d_out;                    // [8,1024,1024]

    dim3 g1(OQKV / 128, (Bsz * Nseq) / 128);       // (24, 64)
    qkv_gemm<<<g1, 256>>>(x, w_qkv);

    dim3 g2(Bsz * Hn, Nseq / 128);                 // (128, 8)
    attn_kernel<<<g2, 128>>>();

    dim3 g3(Cdim / 128, (Bsz * Nseq) / 128);       // (8, 64)
    proj_gemm<<<g3, 256>>>(w_proj, b_proj, out);
}

// round 4
// speedup vs baseline: 1.4926x; 1.4926x over previous
#include <cuda_runtime.h>
#include <cuda_bf16.h>
#include <math_constants.h>
#include <cstdint>

#define Bsz  8
#define Nseq 1024
#define Cdim 1024
#define Hn   16
#define Dh   64
#define Mrows (Bsz * Nseq)
#define OQKV 3072

// ---------------------------------------------------------------------------
// Device-global scratch (allocation-free rule)
// ---------------------------------------------------------------------------
__device__ float g_q[Bsz * Hn * Nseq * Dh];
__device__ float g_k[Bsz * Hn * Nseq * Dh];
__device__ float g_v[Bsz * Hn * Nseq * Dh];

__device__ __nv_bfloat16 g_xhi[Mrows * Cdim];
__device__ __nv_bfloat16 g_xlo[Mrows * Cdim];
__device__ __nv_bfloat16 g_wqhi[OQKV * Cdim];
__device__ __nv_bfloat16 g_wqlo[OQKV * Cdim];
__device__ __nv_bfloat16 g_wphi[Cdim * Cdim];
__device__ __nv_bfloat16 g_wplo[Cdim * Cdim];
__device__ __nv_bfloat16 g_aohi[Mrows * Cdim];
__device__ __nv_bfloat16 g_aolo[Mrows * Cdim];

// ---------------------------------------------------------------------------
// PTX helpers (base ISA only: ldmatrix / mma.sync / cp.async)
// ---------------------------------------------------------------------------
__device__ __forceinline__ uint32_t s2u(const void* p) {
    uint32_t a;
    asm("{ .reg .u64 t; cvta.to.shared.u64 t, %1; cvt.u32.u64 %0, t; }"
        : "=r"(a) : "l"(p));
    return a;
}

__device__ __forceinline__ void ldsm4(uint32_t* r, uint32_t addr) {
    asm volatile("ldmatrix.sync.aligned.m8n8.x4.shared.b16 {%0,%1,%2,%3}, [%4];"
                 : "=r"(r[0]), "=r"(r[1]), "=r"(r[2]), "=r"(r[3]) : "r"(addr));
}

__device__ __forceinline__ void mma16816(float* c, const uint32_t* a,
                                         const uint32_t* b) {
    asm volatile(
        "mma.sync.aligned.m16n8k16.row.col.f32.bf16.bf16.f32 "
        "{%0,%1,%2,%3}, {%4,%5,%6,%7}, {%8,%9}, {%0,%1,%2,%3};"
        : "+f"(c[0]), "+f"(c[1]), "+f"(c[2]), "+f"(c[3])
        : "r"(a[0]), "r"(a[1]), "r"(a[2]), "r"(a[3]), "r"(b[0]), "r"(b[1]));
}

__device__ __forceinline__ void cpa16(uint32_t saddr, const void* g) {
    asm volatile("cp.async.cg.shared.global [%0], [%1], 16;"
                 :: "r"(saddr), "l"(g));
}
#define CP_COMMIT asm volatile("cp.async.commit_group;")
#define CP_WAIT(n) asm volatile("cp.async.wait_group %0;" :: "n"(n))

// ---------------------------------------------------------------------------
// fp32 -> (bf16 hi, bf16 lo) split pre-pass.  which: 0=x, 1=w_qkv, 2=w_proj
// ---------------------------------------------------------------------------
__device__ __forceinline__ uint32_t packsplit(float a, float b, uint32_t& lo_out) {
    __nv_bfloat16 ha = __float2bfloat16_rn(a);
    __nv_bfloat16 hb = __float2bfloat16_rn(b);
    __nv_bfloat162 hp; hp.x = ha; hp.y = hb;
    __nv_bfloat162 lp = __floats2bfloat162_rn(a - __bfloat162float(ha),
                                              b - __bfloat162float(hb));
    lo_out = reinterpret_cast<uint32_t&>(lp);
    return reinterpret_cast<uint32_t&>(hp);
}

__global__ __launch_bounds__(256) void cvt_hilo(const float4* __restrict__ in,
                                                int which, int n4) {
    int i = blockIdx.x * blockDim.x + threadIdx.x;
    if (i >= n4) return;
    uint2* hi; uint2* lo;
    if (which == 0)      { hi = (uint2*)g_xhi;  lo = (uint2*)g_xlo;  }
    else if (which == 1) { hi = (uint2*)g_wqhi; lo = (uint2*)g_wqlo; }
    else                 { hi = (uint2*)g_wphi; lo = (uint2*)g_wplo; }
    float4 v = in[i];
    uint2 H, L;
    H.x = packsplit(v.x, v.y, L.x);
    H.y = packsplit(v.z, v.w, L.y);
    hi[i] = H;
    lo[i] = L;
}

// ---------------------------------------------------------------------------
// bf16x3 mma.sync GEMM: C[m,o] = sum_k A[m,k]*B[o,k]
// CTA tile 128x128, warp tile 64x32 (8 warps, 2x4), K-chunk 32, 3-stage
// cp.async pipeline. Smem pitch 80B (ldmatrix conflict-free).
// mode 0: scatter fp32 into g_q/g_k/g_v [B,H,N,D];  mode 1: +bias -> out.
// ---------------------------------------------------------------------------
#define KC    32
#define PITCH 80                       // bytes per smem row
#define REGB  (128 * PITCH)            // 10240 bytes per matrix region
#define BUFB  (4 * REGB)               // 40960 bytes per stage
#define NSTAGE 3
#define GEMM_SMEM (NSTAGE * BUFB)      // 122880

__global__ __launch_bounds__(256) void gemm_mma(int mode,
                                                const float* __restrict__ bias,
                                                float* __restrict__ out) {
    extern __shared__ char smem[];
    const uint32_t sb = s2u(smem);
    const int tid = threadIdx.x;
    const int m0 = blockIdx.y * 128;
    const int o0 = blockIdx.x * 128;

    const __nv_bfloat16* Ahi = ((mode == 0) ? g_xhi  : g_aohi) + (size_t)m0 * Cdim;
    const __nv_bfloat16* Alo = ((mode == 0) ? g_xlo  : g_aolo) + (size_t)m0 * Cdim;
    const __nv_bfloat16* Bhi = ((mode == 0) ? g_wqhi : g_wphi) + (size_t)o0 * Cdim;
    const __nv_bfloat16* Blo = ((mode == 0) ? g_wqlo : g_wplo) + (size_t)o0 * Cdim;
    const __nv_bfloat16* srcs[4] = {Ahi, Alo, Bhi, Blo};

    // per-thread load slots: 2 uint4 per matrix region per chunk
    const int lrow0 = tid >> 2;            // idx = tid      -> row, c8
    const int lc80  = tid & 3;
    const int lrow1 = (256 + tid) >> 2;    // idx = 256+tid
    const int lc81  = tid & 3;             // (256+tid)&3 == tid&3

    auto issue = [&](int c, int stage) {
        uint32_t s0 = sb + stage * BUFB;
        const int ko = c * KC;
#pragma unroll
        for (int mt = 0; mt < 4; mt++) {
            cpa16(s0 + mt * REGB + lrow0 * PITCH + lc80 * 16,
                  srcs[mt] + lrow0 * Cdim + ko + lc80 * 8);
            cpa16(s0 + mt * REGB + lrow1 * PITCH + lc81 * 16,
                  srcs[mt] + lrow1 * Cdim + ko + lc81 * 8);
        }
    };

    const int wid = tid >> 5, lane = tid & 31;
    const int wm = wid >> 2;   // 0..1 -> m offset wm*64
    const int wn = wid & 3;    // 0..3 -> n offset wn*32

    // ldmatrix lane address components
    const int a_row  = wm * 64 + (lane & 15);          // + mb*16
    const int a_colb = (lane >> 4) * 16;               // + ks*32  (bytes)
    const int b_row  = wn * 32 + ((lane >> 4) << 3) + (lane & 7);  // + nbp*16
    const int b_colb = ((lane >> 3) & 1) * 16;         // + ks*32  (bytes)

    float acc[4][4][4];
#pragma unroll
    for (int i = 0; i < 4; i++)
#pragma unroll
        for (int j = 0; j < 4; j++)
#pragma unroll
            for (int k = 0; k < 4; k++) acc[i][j][k] = 0.0f;

    issue(0, 0); CP_COMMIT;
    issue(1, 1); CP_COMMIT;

    const int NCH = Cdim / KC;   // 32
    for (int c = 0; c < NCH; c++) {
        if (c + 2 < NCH) { issue(c + 2, (c + 2) % NSTAGE); CP_COMMIT; CP_WAIT(2); }
        else if (c + 1 < NCH) { CP_WAIT(1); }
        else { CP_WAIT(0); }
        __syncthreads();

        const uint32_t base = sb + (c % NSTAGE) * BUFB;
#pragma unroll
        for (int ks = 0; ks < 2; ks++) {
            uint32_t Ah[4][4], Al[4][4], Bh[2][4], Bl[2][4];
#pragma unroll
            for (int mb = 0; mb < 4; mb++) {
                uint32_t ra = base + (a_row + mb * 16) * PITCH + ks * 32 + a_colb;
                ldsm4(Ah[mb], ra);
                ldsm4(Al[mb], ra + REGB);
            }
#pragma unroll
            for (int nbp = 0; nbp < 2; nbp++) {
                uint32_t rb = base + 2 * REGB + (b_row + nbp * 16) * PITCH
                            + ks * 32 + b_colb;
                ldsm4(Bh[nbp], rb);
                ldsm4(Bl[nbp], rb + REGB);
            }
#pragma unroll
            for (int mb = 0; mb < 4; mb++)
#pragma unroll
                for (int nb = 0; nb < 4; nb++) {
                    const uint32_t* bh = &Bh[nb >> 1][(nb & 1) * 2];
                    const uint32_t* bl = &Bl[nb >> 1][(nb & 1) * 2];
                    mma16816(acc[mb][nb], Ah[mb], bh);
                    mma16816(acc[mb][nb], Ah[mb], bl);
                    mma16816(acc[mb][nb], Al[mb], bh);
                }
        }
        __syncthreads();
    }

    // Epilogue. c-frag layout: c0=(r, col), c1=(r, col+1), c2=(r+8, col), c3.
    const int erow = m0 + wm * 64 + (lane >> 2);
    const int ecol = o0 + wn * 32 + (lane & 3) * 2;
    if (mode == 0) {
        const int which = o0 >> 10;
        float* bufp = (which == 0) ? g_q : (which == 1) ? g_k : g_v;
#pragma unroll
        for (int mb = 0; mb < 4; mb++) {
            const int m = erow + mb * 16;
            const int bb = m >> 10, n = m & 1023;
#pragma unroll
            for (int nb = 0; nb < 4; nb++) {
                const int o = ecol + nb * 8;
                const int h = (o & 1023) >> 6;
                const int d = o & 63;
                float* dst = bufp + (((size_t)(bb * Hn + h) * Nseq + n) * Dh + d);
                *(float2*)dst = make_float2(acc[mb][nb][0], acc[mb][nb][1]);
                *(float2*)(dst + 8 * Dh) = make_float2(acc[mb][nb][2], acc[mb][nb][3]);
            }
        }
    } else {
#pragma unroll
        for (int mb = 0; mb < 4; mb++) {
            const int m = erow + mb * 16;
#pragma unroll
            for (int nb = 0; nb < 4; nb++) {
                const int o = ecol + nb * 8;
                const float2 bv = *(const float2*)(bias + o);
                float* dst = out + (size_t)m * Cdim + o;
                *(float2*)dst = make_float2(acc[mb][nb][0] + bv.x,
                                            acc[mb][nb][1] + bv.y);
                *(float2*)(dst + 8 * Cdim) = make_float2(acc[mb][nb][2] + bv.x,
                                                         acc[mb][nb][3] + bv.y);
            }
        }
    }
}

// ---------------------------------------------------------------------------
// Flash attention, fp32; epilogue emits bf16 hi/lo for the projection GEMM.
// ---------------------------------------------------------------------------
__global__ __launch_bounds__(128) void attn_kernel() {
    const int bh  = blockIdx.x;
    const int row = blockIdx.y * 128 + threadIdx.x;
    const float* Qp = g_q + bh * (Nseq * Dh);
    const float* Kp = g_k + bh * (Nseq * Dh);
    const float* Vp = g_v + bh * (Nseq * Dh);

    __shared__ float4 Ks[16][16];
    __shared__ float4 Vs[16][16];

    const float qs = 0.125f * 1.44269504088896340736f;
    float q[64];
#pragma unroll
    for (int d4 = 0; d4 < 16; d4++) {
        float4 t = ((const float4*)(Qp + row * Dh))[d4];
        q[d4 * 4 + 0] = t.x * qs; q[d4 * 4 + 1] = t.y * qs;
        q[d4 * 4 + 2] = t.z * qs; q[d4 * 4 + 3] = t.w * qs;
    }

    float o[64];
#pragma unroll
    for (int d = 0; d < 64; d++) o[d] = 0.0f;
    float mi = -CUDART_INF_F;
    float li = 0.0f;

    for (int j0 = 0; j0 < Nseq; j0 += 16) {
        const float4* ksrc = (const float4*)(Kp + j0 * Dh);
        const float4* vsrc = (const float4*)(Vp + j0 * Dh);
        ((float4*)Ks)[threadIdx.x]       = ksrc[threadIdx.x];
        ((float4*)Ks)[threadIdx.x + 128] = ksrc[threadIdx.x + 128];
        ((float4*)Vs)[threadIdx.x]       = vsrc[threadIdx.x];
        ((float4*)Vs)[threadIdx.x + 128] = vsrc[threadIdx.x + 128];
        __syncthreads();

        float s[16];
        float tmax = -CUDART_INF_F;
#pragma unroll
        for (int r = 0; r < 16; r++) {
            float accv = 0.0f;
#pragma unroll
            for (int d4 = 0; d4 < 16; d4++) {
                float4 kv = Ks[r][d4];
                accv = fmaf(q[d4 * 4 + 0], kv.x, accv);
                accv = fmaf(q[d4 * 4 + 1], kv.y, accv);
                accv = fmaf(q[d4 * 4 + 2], kv.z, accv);
                accv = fmaf(q[d4 * 4 + 3], kv.w, accv);
            }
            s[r] = accv;
            tmax = fmaxf(tmax, accv);
        }

        float mnew  = fmaxf(mi, tmax);
        float alpha = exp2f(mi - mnew);
        li *= alpha;
#pragma unroll
        for (int d = 0; d < 64; d++) o[d] *= alpha;

#pragma unroll
        for (int r = 0; r < 16; r++) {
            float p = exp2f(s[r] - mnew);
            li += p;
#pragma unroll
            for (int d4 = 0; d4 < 16; d4++) {
                float4 vv = Vs[r][d4];
                o[d4 * 4 + 0] = fmaf(p, vv.x, o[d4 * 4 + 0]);
                o[d4 * 4 + 1] = fmaf(p, vv.y, o[d4 * 4 + 1]);
                o[d4 * 4 + 2] = fmaf(p, vv.z, o[d4 * 4 + 2]);
                o[d4 * 4 + 3] = fmaf(p, vv.w, o[d4 * 4 + 3]);
            }
        }
        mi = mnew;
        __syncthreads();
    }

    const float inv = 1.0f / li;
    const int b = bh >> 4;
    const int h = bh & 15;
    const size_t base = ((size_t)(b * Nseq + row) * Cdim + h * Dh);
    uint2* dh = (uint2*)(g_aohi + base);
    uint2* dl = (uint2*)(g_aolo + base);
#pragma unroll
    for (int g = 0; g < 16; g++) {
        uint2 H, L;
        H.x = packsplit(o[4 * g + 0] * inv, o[4 * g + 1] * inv, L.x);
        H.y = packsplit(o[4 * g + 2] * inv, o[4 * g + 3] * inv, L.y);
        dh[g] = H;
        dl[g] = L;
    }
}

// ---------------------------------------------------------------------------
extern "C" void kernel_launch(void* const* d_in, const int* in_sizes, int n_in,
                              void* d_out, int out_size) {
    const float* x      = (const float*)d_in[0];   // [8,1024,1024]
    const float* w_qkv  = (const float*)d_in[1];   // [3072,1024]
    const float* w_proj = (const float*)d_in[2];   // [1024,1024]
    const float* b_proj = (const float*)d_in[3];   // [1024]
    float* out = (float*)d_out;

    static bool attr_done = false;
    if (!attr_done) {
        cudaFuncSetAttribute(gemm_mma,
                             cudaFuncAttributeMaxDynamicSharedMemorySize,
                             GEMM_SMEM);
        attr_done = true;
    }

    {
        int n4 = (Mrows * Cdim) / 4;
        cvt_hilo<<<(n4 + 255) / 256, 256>>>((const float4*)x, 0, n4);
    }
    {
        int n4 = (OQKV * Cdim) / 4;
        cvt_hilo<<<(n4 + 255) / 256, 256>>>((const float4*)w_qkv, 1, n4);
    }
    {
        int n4 = (Cdim * Cdim) / 4;
        cvt_hilo<<<(n4 + 255) / 256, 256>>>((const float4*)w_proj, 2, n4);
    }

    dim3 g1(OQKV / 128, Mrows / 128);              // (24, 64)
    gemm_mma<<<g1, 256, GEMM_SMEM>>>(0, nullptr, nullptr);

    dim3 g2(Bsz * Hn, Nseq / 128);                 // (128, 8)
    attn_kernel<<<g2, 128>>>();

    dim3 g3(Cdim / 128, Mrows / 128);              // (8, 64)
    gemm_mma<<<g3, 256, GEMM_SMEM>>>(1, b_proj, out);
}

// round 5
// speedup vs baseline: 3.5887x; 2.4044x over previous
#include <cuda_runtime.h>
#include <cuda_bf16.h>
#include <math_constants.h>
#include <cstdint>

#define Bsz  8
#define Nseq 1024
#define Cdim 1024
#define Hn   16
#define Dh   64
#define Mrows (Bsz * Nseq)
#define OQKV 3072

// ---------------------------------------------------------------------------
// Device-global scratch (allocation-free rule)
// ---------------------------------------------------------------------------
__device__ __nv_bfloat16 g_xhi[Mrows * Cdim];
__device__ __nv_bfloat16 g_xlo[Mrows * Cdim];
__device__ __nv_bfloat16 g_wqhi[OQKV * Cdim];
__device__ __nv_bfloat16 g_wqlo[OQKV * Cdim];
__device__ __nv_bfloat16 g_wphi[Cdim * Cdim];
__device__ __nv_bfloat16 g_wplo[Cdim * Cdim];
__device__ __nv_bfloat16 g_aohi[Mrows * Cdim];
__device__ __nv_bfloat16 g_aolo[Mrows * Cdim];

// Q/K/V split buffers, layout [b*H+h][n][d], d contiguous. Q pre-scaled.
__device__ __nv_bfloat16 g_qhi[Bsz * Hn * Nseq * Dh];
__device__ __nv_bfloat16 g_qlo[Bsz * Hn * Nseq * Dh];
__device__ __nv_bfloat16 g_khi[Bsz * Hn * Nseq * Dh];
__device__ __nv_bfloat16 g_klo[Bsz * Hn * Nseq * Dh];
__device__ __nv_bfloat16 g_vhi[Bsz * Hn * Nseq * Dh];
__device__ __nv_bfloat16 g_vlo[Bsz * Hn * Nseq * Dh];

// ---------------------------------------------------------------------------
// PTX helpers (base ISA: ldmatrix / mma.sync / cp.async)
// ---------------------------------------------------------------------------
__device__ __forceinline__ uint32_t s2u(const void* p) {
    uint32_t a;
    asm("{ .reg .u64 t; cvta.to.shared.u64 t, %1; cvt.u32.u64 %0, t; }"
        : "=r"(a) : "l"(p));
    return a;
}

__device__ __forceinline__ void ldsm4(uint32_t* r, uint32_t addr) {
    asm volatile("ldmatrix.sync.aligned.m8n8.x4.shared.b16 {%0,%1,%2,%3}, [%4];"
                 : "=r"(r[0]), "=r"(r[1]), "=r"(r[2]), "=r"(r[3]) : "r"(addr));
}

__device__ __forceinline__ void ldsm4t(uint32_t* r, uint32_t addr) {
    asm volatile("ldmatrix.sync.aligned.m8n8.x4.trans.shared.b16 {%0,%1,%2,%3}, [%4];"
                 : "=r"(r[0]), "=r"(r[1]), "=r"(r[2]), "=r"(r[3]) : "r"(addr));
}

__device__ __forceinline__ void mma16816(float* c, const uint32_t* a,
                                         const uint32_t* b) {
    asm volatile(
        "mma.sync.aligned.m16n8k16.row.col.f32.bf16.bf16.f32 "
        "{%0,%1,%2,%3}, {%4,%5,%6,%7}, {%8,%9}, {%0,%1,%2,%3};"
        : "+f"(c[0]), "+f"(c[1]), "+f"(c[2]), "+f"(c[3])
        : "r"(a[0]), "r"(a[1]), "r"(a[2]), "r"(a[3]), "r"(b[0]), "r"(b[1]));
}

__device__ __forceinline__ void cpa16(uint32_t saddr, const void* g) {
    asm volatile("cp.async.cg.shared.global [%0], [%1], 16;"
                 :: "r"(saddr), "l"(g));
}
#define CP_COMMIT asm volatile("cp.async.commit_group;")
#define CP_WAIT(n) asm volatile("cp.async.wait_group %0;" :: "n"(n))

__device__ __forceinline__ float ex2(float x) {
    float r;
    asm("ex2.approx.ftz.f32 %0, %1;" : "=f"(r) : "f"(x));
    return r;
}

__device__ __forceinline__ uint32_t packsplit(float a, float b, uint32_t& lo_out) {
    __nv_bfloat16 ha = __float2bfloat16_rn(a);
    __nv_bfloat16 hb = __float2bfloat16_rn(b);
    __nv_bfloat162 hp; hp.x = ha; hp.y = hb;
    __nv_bfloat162 lp = __floats2bfloat162_rn(a - __bfloat162float(ha),
                                              b - __bfloat162float(hb));
    lo_out = reinterpret_cast<uint32_t&>(lp);
    return reinterpret_cast<uint32_t&>(hp);
}

// ---------------------------------------------------------------------------
// fp32 -> (bf16 hi, bf16 lo) split pre-pass for GEMM inputs.
// ---------------------------------------------------------------------------
__global__ __launch_bounds__(256) void cvt_hilo(const float4* __restrict__ in,
                                                int which, int n4) {
    int i = blockIdx.x * blockDim.x + threadIdx.x;
    if (i >= n4) return;
    uint2* hi; uint2* lo;
    if (which == 0)      { hi = (uint2*)g_xhi;  lo = (uint2*)g_xlo;  }
    else if (which == 1) { hi = (uint2*)g_wqhi; lo = (uint2*)g_wqlo; }
    else                 { hi = (uint2*)g_wphi; lo = (uint2*)g_wplo; }
    float4 v = in[i];
    uint2 H, L;
    H.x = packsplit(v.x, v.y, L.x);
    H.y = packsplit(v.z, v.w, L.y);
    hi[i] = H;
    lo[i] = L;
}

// ---------------------------------------------------------------------------
// bf16x3 mma.sync GEMM. CTA 128x128, 8 warps (64x32 each), K-chunk 32,
// 2-stage cp.async (80KB smem -> 2 CTAs/SM).
// mode 0: split-write q/k/v (q pre-scaled);  mode 1: +bias -> out.
// ---------------------------------------------------------------------------
#define KC    32
#define PITCH 80
#define REGB  (128 * PITCH)
#define BUFB  (4 * REGB)
#define NSTAGE 2
#define GEMM_SMEM (NSTAGE * BUFB)      // 81920

__global__ __launch_bounds__(256, 2) void gemm_mma(int mode,
                                                   const float* __restrict__ bias,
                                                   float* __restrict__ out) {
    extern __shared__ char smem[];
    const uint32_t sb = s2u(smem);
    const int tid = threadIdx.x;
    const int m0 = blockIdx.y * 128;
    const int o0 = blockIdx.x * 128;

    const __nv_bfloat16* Ahi = ((mode == 0) ? g_xhi  : g_aohi) + (size_t)m0 * Cdim;
    const __nv_bfloat16* Alo = ((mode == 0) ? g_xlo  : g_aolo) + (size_t)m0 * Cdim;
    const __nv_bfloat16* Bhi = ((mode == 0) ? g_wqhi : g_wphi) + (size_t)o0 * Cdim;
    const __nv_bfloat16* Blo = ((mode == 0) ? g_wqlo : g_wplo) + (size_t)o0 * Cdim;
    const __nv_bfloat16* srcs[4] = {Ahi, Alo, Bhi, Blo};

    const int lrow0 = tid >> 2;
    const int lc80  = tid & 3;
    const int lrow1 = (256 + tid) >> 2;

    auto issue = [&](int c, int stage) {
        uint32_t s0 = sb + stage * BUFB;
        const int ko = c * KC;
#pragma unroll
        for (int mt = 0; mt < 4; mt++) {
            cpa16(s0 + mt * REGB + lrow0 * PITCH + lc80 * 16,
                  srcs[mt] + lrow0 * Cdim + ko + lc80 * 8);
            cpa16(s0 + mt * REGB + lrow1 * PITCH + lc80 * 16,
                  srcs[mt] + lrow1 * Cdim + ko + lc80 * 8);
        }
    };

    const int wid = tid >> 5, lane = tid & 31;
    const int wm = wid >> 2;
    const int wn = wid & 3;

    const int a_row  = wm * 64 + (lane & 15);
    const int a_colb = (lane >> 4) * 16;
    const int b_row  = wn * 32 + ((lane >> 4) << 3) + (lane & 7);
    const int b_colb = ((lane >> 3) & 1) * 16;

    float acc[4][4][4];
#pragma unroll
    for (int i = 0; i < 4; i++)
#pragma unroll
        for (int j = 0; j < 4; j++)
#pragma unroll
            for (int k = 0; k < 4; k++) acc[i][j][k] = 0.0f;

    issue(0, 0); CP_COMMIT;
    issue(1, 1); CP_COMMIT;

    const int NCH = Cdim / KC;   // 32
    for (int c = 0; c < NCH; c++) {
        if (c + 1 < NCH) { CP_WAIT(1); } else { CP_WAIT(0); }
        __syncthreads();

        const uint32_t base = sb + (c & 1) * BUFB;
#pragma unroll
        for (int ks = 0; ks < 2; ks++) {
            uint32_t Ah[4][4], Al[4][4], Bh[2][4], Bl[2][4];
#pragma unroll
            for (int mb = 0; mb < 4; mb++) {
                uint32_t ra = base + (a_row + mb * 16) * PITCH + ks * 32 + a_colb;
                ldsm4(Ah[mb], ra);
                ldsm4(Al[mb], ra + REGB);
            }
#pragma unroll
            for (int nbp = 0; nbp < 2; nbp++) {
                uint32_t rb = base + 2 * REGB + (b_row + nbp * 16) * PITCH
                            + ks * 32 + b_colb;
                ldsm4(Bh[nbp], rb);
                ldsm4(Bl[nbp], rb + REGB);
            }
#pragma unroll
            for (int mb = 0; mb < 4; mb++)
#pragma unroll
                for (int nb = 0; nb < 4; nb++) {
                    const uint32_t* bh = &Bh[nb >> 1][(nb & 1) * 2];
                    const uint32_t* bl = &Bl[nb >> 1][(nb & 1) * 2];
                    mma16816(acc[mb][nb], Ah[mb], bh);
                    mma16816(acc[mb][nb], Ah[mb], bl);
                    mma16816(acc[mb][nb], Al[mb], bh);
                }
        }
        __syncthreads();
        if (c + 2 < NCH) { issue(c + 2, c & 1); CP_COMMIT; }
    }

    const int erow = m0 + wm * 64 + (lane >> 2);
    const int ecol = o0 + wn * 32 + (lane & 3) * 2;
    if (mode == 0) {
        const int which = o0 >> 10;
        __nv_bfloat16 *hip, *lop;
        float sc;
        const float qs = 0.125f * 1.44269504088896340736f;
        if (which == 0)      { hip = g_qhi; lop = g_qlo; sc = qs; }
        else if (which == 1) { hip = g_khi; lop = g_klo; sc = 1.0f; }
        else                 { hip = g_vhi; lop = g_vlo; sc = 1.0f; }
#pragma unroll
        for (int mb = 0; mb < 4; mb++) {
            const int m = erow + mb * 16;
            const int bb = m >> 10, n = m & 1023;
#pragma unroll
            for (int nb = 0; nb < 4; nb++) {
                const int o = ecol + nb * 8;
                const int h = (o & 1023) >> 6;
                const int d = o & 63;
                size_t base = ((size_t)(bb * Hn + h) * Nseq + n) * Dh + d;
                uint32_t L0, L1;
                uint32_t H0 = packsplit(acc[mb][nb][0] * sc, acc[mb][nb][1] * sc, L0);
                uint32_t H1 = packsplit(acc[mb][nb][2] * sc, acc[mb][nb][3] * sc, L1);
                *(uint32_t*)(hip + base)            = H0;
                *(uint32_t*)(lop + base)            = L0;
                *(uint32_t*)(hip + base + 8 * Dh)   = H1;
                *(uint32_t*)(lop + base + 8 * Dh)   = L1;
            }
        }
    } else {
#pragma unroll
        for (int mb = 0; mb < 4; mb++) {
            const int m = erow + mb * 16;
#pragma unroll
            for (int nb = 0; nb < 4; nb++) {
                const int o = ecol + nb * 8;
                const float2 bv = *(const float2*)(bias + o);
                float* dst = out + (size_t)m * Cdim + o;
                *(float2*)dst = make_float2(acc[mb][nb][0] + bv.x,
                                            acc[mb][nb][1] + bv.y);
                *(float2*)(dst + 8 * Cdim) = make_float2(acc[mb][nb][2] + bv.x,
                                                         acc[mb][nb][3] + bv.y);
            }
        }
    }
}

// ---------------------------------------------------------------------------
// Flash attention via mma.sync bf16x3.
// CTA: 128 Q rows x one (b,h). 8 warps, 16 Q rows each. KV streamed in
// 128-row tiles, 2-stage cp.async. S/P in f32 C-frags; P split to bf16 hi/lo
// in-register (C-frag layout == next A-frag layout).
// ---------------------------------------------------------------------------
#define APITCH 144                       // 64 bf16 + 8 pad = 144B row
#define AREG   (128 * APITCH)            // 18432 per matrix tile
#define AQH    0
#define AQL    AREG
#define AKV0   (2 * AREG)                // stage base
#define ASTAGE (4 * AREG)                // Kh,Kl,Vh,Vl per stage = 73728
#define ATTN_SMEM (2 * AREG + 2 * ASTAGE)  // 184320

__global__ __launch_bounds__(256) void attn_mma() {
    extern __shared__ char smem[];
    const uint32_t sb = s2u(smem);
    const int tid = threadIdx.x;
    const int w = tid >> 5, lane = tid & 31;
    const int bh = blockIdx.x;           // 0..127
    const int qb = blockIdx.y;           // 0..7

    const size_t hoff = (size_t)bh * (Nseq * Dh);
    const __nv_bfloat16* qh = g_qhi + hoff + (size_t)qb * 128 * Dh;
    const __nv_bfloat16* ql = g_qlo + hoff + (size_t)qb * 128 * Dh;

    // --- async loads -------------------------------------------------------
    auto loadQ = [&]() {
#pragma unroll
        for (int j = 0; j < 8; j++) {
            int idx = j * 256 + tid;          // 0..2047
            int mt  = j >> 2;                 // 0=hi 1=lo
            int r   = (idx >> 3) & 127;
            int c8  = idx & 7;
            const __nv_bfloat16* src = mt ? ql : qh;
            cpa16(sb + mt * AREG + r * APITCH + c8 * 16, src + r * Dh + c8 * 8);
        }
    };
    auto loadKV = [&](int kb, int st) {
        const size_t koff = hoff + (size_t)kb * 128 * Dh;
        const __nv_bfloat16* srcs[4] = {g_khi + koff, g_klo + koff,
                                        g_vhi + koff, g_vlo + koff};
        uint32_t base = sb + AKV0 + st * ASTAGE;
#pragma unroll
        for (int j = 0; j < 16; j++) {
            int idx = j * 256 + tid;          // 0..4095
            int mt  = j >> 2;                 // matrix 0..3
            int r   = (idx >> 3) & 127;
            int c8  = idx & 7;
            cpa16(base + mt * AREG + r * APITCH + c8 * 16,
                  srcs[mt] + r * Dh + c8 * 8);
        }
    };

    loadQ();          CP_COMMIT;
    loadKV(0, 0);     CP_COMMIT;
    loadKV(1, 1);     CP_COMMIT;

    // --- per-warp frag addresses ------------------------------------------
    const int a_rowb = (w * 16 + (lane & 15)) * APITCH + (lane >> 4) * 16;
    const int k_rowi = ((lane >> 4) << 3) + (lane & 7);      // + ng*16
    const int k_colb = ((lane >> 3) & 1) * 16;               // + kc*32
    const int v_rowi = (lane & 7) + ((lane >> 3) & 1) * 8;   // + kc2*16
    const int v_colb = (lane >> 4) * 16;                     // + dg*32

    CP_WAIT(2);       // Q resident
    __syncthreads();

    uint32_t QAh[4][4], QAl[4][4];
#pragma unroll
    for (int kc = 0; kc < 4; kc++) {
        uint32_t ra = sb + a_rowb + kc * 32;
        ldsm4(QAh[kc], ra + AQH);
        ldsm4(QAl[kc], ra + AQL);
    }

    float O[8][4];
#pragma unroll
    for (int i = 0; i < 8; i++)
#pragma unroll
        for (int j = 0; j < 4; j++) O[i][j] = 0.0f;
    float m0 = -1e30f, m1 = -1e30f;
    float l0 = 0.0f, l1 = 0.0f;

    for (int kb = 0; kb < 8; kb++) {
        if (kb + 1 < 8) { CP_WAIT(1); } else { CP_WAIT(0); }
        __syncthreads();
        const uint32_t kbase = sb + AKV0 + (kb & 1) * ASTAGE;

        // ----- S = Q K^T (3 passes), 16 n-blocks of 8 ----------------------
        float S[16][4];
#pragma unroll
        for (int i = 0; i < 16; i++)
#pragma unroll
            for (int j = 0; j < 4; j++) S[i][j] = 0.0f;

#pragma unroll
        for (int ng = 0; ng < 8; ng++) {
#pragma unroll
            for (int kc = 0; kc < 4; kc++) {
                uint32_t kbh[4], kbl[4];
                uint32_t rb = kbase + (ng * 16 + k_rowi) * APITCH
                            + k_colb + kc * 32;
                ldsm4(kbh, rb);
                ldsm4(kbl, rb + AREG);
#pragma unroll
                for (int half = 0; half < 2; half++) {
                    float* s = S[ng * 2 + half];
                    mma16816(s, QAh[kc], &kbh[half * 2]);
                    mma16816(s, QAh[kc], &kbl[half * 2]);
                    mma16816(s, QAl[kc], &kbh[half * 2]);
                }
            }
        }

        // ----- online softmax ---------------------------------------------
        float rm0 = -1e30f, rm1 = -1e30f;
#pragma unroll
        for (int i = 0; i < 16; i++) {
            rm0 = fmaxf(rm0, fmaxf(S[i][0], S[i][1]));
            rm1 = fmaxf(rm1, fmaxf(S[i][2], S[i][3]));
        }
        rm0 = fmaxf(rm0, __shfl_xor_sync(0xffffffffu, rm0, 1));
        rm0 = fmaxf(rm0, __shfl_xor_sync(0xffffffffu, rm0, 2));
        rm1 = fmaxf(rm1, __shfl_xor_sync(0xffffffffu, rm1, 1));
        rm1 = fmaxf(rm1, __shfl_xor_sync(0xffffffffu, rm1, 2));

        float mn0 = fmaxf(m0, rm0), mn1 = fmaxf(m1, rm1);
        float al0 = ex2(m0 - mn0),  al1 = ex2(m1 - mn1);
        m0 = mn0; m1 = mn1;
        l0 *= al0; l1 *= al1;
#pragma unroll
        for (int i = 0; i < 8; i++) {
            O[i][0] *= al0; O[i][1] *= al0;
            O[i][2] *= al1; O[i][3] *= al1;
        }
        float ps0 = 0.0f, ps1 = 0.0f;
#pragma unroll
        for (int i = 0; i < 16; i++) {
            S[i][0] = ex2(S[i][0] - mn0);
            S[i][1] = ex2(S[i][1] - mn0);
            S[i][2] = ex2(S[i][2] - mn1);
            S[i][3] = ex2(S[i][3] - mn1);
            ps0 += S[i][0] + S[i][1];
            ps1 += S[i][2] + S[i][3];
        }
        l0 += ps0; l1 += ps1;

        // ----- O += P V (3 passes) ----------------------------------------
#pragma unroll
        for (int kc2 = 0; kc2 < 8; kc2++) {
            uint32_t pah[4], pal[4];
            pah[0] = packsplit(S[2 * kc2][0],     S[2 * kc2][1],     pal[0]);
            pah[1] = packsplit(S[2 * kc2][2],     S[2 * kc2][3],     pal[1]);
            pah[2] = packsplit(S[2 * kc2 + 1][0], S[2 * kc2 + 1][1], pal[2]);
            pah[3] = packsplit(S[2 * kc2 + 1][2], S[2 * kc2 + 1][3], pal[3]);
#pragma unroll
            for (int dg = 0; dg < 4; dg++) {
                uint32_t vbh[4], vbl[4];
                uint32_t rv = kbase + 2 * AREG
                            + (kc2 * 16 + v_rowi) * APITCH + v_colb + dg * 32;
                ldsm4t(vbh, rv);
                ldsm4t(vbl, rv + AREG);
#pragma unroll
                for (int half = 0; half < 2; half++) {
                    float* o = O[dg * 2 + half];
                    mma16816(o, pah, &vbh[half * 2]);
                    mma16816(o, pah, &vbl[half * 2]);
                    mma16816(o, pal, &vbh[half * 2]);
                }
            }
        }

        __syncthreads();
        if (kb + 2 < 8) { loadKV(kb + 2, kb & 1); CP_COMMIT; }
    }

    // ----- finalize + write bf16 hi/lo for proj GEMM -----------------------
    l0 += __shfl_xor_sync(0xffffffffu, l0, 1);
    l0 += __shfl_xor_sync(0xffffffffu, l0, 2);
    l1 += __shfl_xor_sync(0xffffffffu, l1, 1);
    l1 += __shfl_xor_sync(0xffffffffu, l1, 2);
    const float inv0 = 1.0f / l0, inv1 = 1.0f / l1;

    const int b = bh >> 4, h = bh & 15;
    const int n0 = qb * 128 + w * 16 + (lane >> 2);
#pragma unroll
    for (int nb = 0; nb < 8; nb++) {
        const int d = nb * 8 + (lane & 3) * 2;
        size_t base0 = ((size_t)(b * Nseq + n0) * Cdim) + h * Dh + d;
        size_t base1 = base0 + (size_t)8 * Cdim;
        uint32_t L0, L1;
        uint32_t H0 = packsplit(O[nb][0] * inv0, O[nb][1] * inv0, L0);
        uint32_t H1 = packsplit(O[nb][2] * inv1, O[nb][3] * inv1, L1);
        *(uint32_t*)(g_aohi + base0) = H0;
        *(uint32_t*)(g_aolo + base0) = L0;
        *(uint32_t*)(g_aohi + base1) = H1;
        *(uint32_t*)(g_aolo + base1) = L1;
    }
}

// ---------------------------------------------------------------------------
extern "C" void kernel_launch(void* const* d_in, const int* in_sizes, int n_in,
                              void* d_out, int out_size) {
    const float* x      = (const float*)d_in[0];   // [8,1024,1024]
    const float* w_qkv  = (const float*)d_in[1];   // [3072,1024]
    const float* w_proj = (const float*)d_in[2];   // [1024,1024]
    const float* b_proj = (const float*)d_in[3];   // [1024]
    float* out = (float*)d_out;

    static bool attr_done = false;
    if (!attr_done) {
        cudaFuncSetAttribute(gemm_mma,
                             cudaFuncAttributeMaxDynamicSharedMemorySize,
                             GEMM_SMEM);
        cudaFuncSetAttribute(attn_mma,
                             cudaFuncAttributeMaxDynamicSharedMemorySize,
                             ATTN_SMEM);
        attr_done = true;
    }

    {
        int n4 = (Mrows * Cdim) / 4;
        cvt_hilo<<<(n4 + 255) / 256, 256>>>((const float4*)x, 0, n4);
    }
    {
        int n4 = (OQKV * Cdim) / 4;
        cvt_hilo<<<(n4 + 255) / 256, 256>>>((const float4*)w_qkv, 1, n4);
    }
    {
        int n4 = (Cdim * Cdim) / 4;
        cvt_hilo<<<(n4 + 255) / 256, 256>>>((const float4*)w_proj, 2, n4);
    }

    dim3 g1(OQKV / 128, Mrows / 128);              // (24, 64)
    gemm_mma<<<g1, 256, GEMM_SMEM>>>(0, nullptr, nullptr);

    dim3 g2(Bsz * Hn, Nseq / 128);                 // (128, 8)
    attn_mma<<<g2, 256, ATTN_SMEM>>>();

    dim3 g3(Cdim / 128, Mrows / 128);              // (8, 64)
    gemm_mma<<<g3, 256, GEMM_SMEM>>>(1, b_proj, out);
}

// round 6
// speedup vs baseline: 3.7265x; 1.0384x over previous
#include <cuda_runtime.h>
#include <cuda_bf16.h>
#include <math_constants.h>
#include <cstdint>

#define Bsz  8
#define Nseq 1024
#define Cdim 1024
#define Hn   16
#define Dh   64
#define Mrows (Bsz * Nseq)
#define OQKV 3072

// ---------------------------------------------------------------------------
// Device-global scratch (allocation-free rule)
// ---------------------------------------------------------------------------
__device__ __nv_bfloat16 g_xhi[Mrows * Cdim];
__device__ __nv_bfloat16 g_xlo[Mrows * Cdim];
__device__ __nv_bfloat16 g_wqhi[OQKV * Cdim];
__device__ __nv_bfloat16 g_wqlo[OQKV * Cdim];
__device__ __nv_bfloat16 g_wphi[Cdim * Cdim];
__device__ __nv_bfloat16 g_wplo[Cdim * Cdim];
__device__ __nv_bfloat16 g_aohi[Mrows * Cdim];
__device__ __nv_bfloat16 g_aolo[Mrows * Cdim];

// Q/K/V split buffers, layout [b*H+h][n][d], d contiguous. Q pre-scaled.
__device__ __nv_bfloat16 g_qhi[Bsz * Hn * Nseq * Dh];
__device__ __nv_bfloat16 g_qlo[Bsz * Hn * Nseq * Dh];
__device__ __nv_bfloat16 g_khi[Bsz * Hn * Nseq * Dh];
__device__ __nv_bfloat16 g_klo[Bsz * Hn * Nseq * Dh];
__device__ __nv_bfloat16 g_vhi[Bsz * Hn * Nseq * Dh];
__device__ __nv_bfloat16 g_vlo[Bsz * Hn * Nseq * Dh];

// ---------------------------------------------------------------------------
// PTX helpers (base ISA: ldmatrix / mma.sync / cp.async)
// ---------------------------------------------------------------------------
__device__ __forceinline__ uint32_t s2u(const void* p) {
    uint32_t a;
    asm("{ .reg .u64 t; cvta.to.shared.u64 t, %1; cvt.u32.u64 %0, t; }"
        : "=r"(a) : "l"(p));
    return a;
}

__device__ __forceinline__ void ldsm4(uint32_t* r, uint32_t addr) {
    asm volatile("ldmatrix.sync.aligned.m8n8.x4.shared.b16 {%0,%1,%2,%3}, [%4];"
                 : "=r"(r[0]), "=r"(r[1]), "=r"(r[2]), "=r"(r[3]) : "r"(addr));
}

__device__ __forceinline__ void ldsm4t(uint32_t* r, uint32_t addr) {
    asm volatile("ldmatrix.sync.aligned.m8n8.x4.trans.shared.b16 {%0,%1,%2,%3}, [%4];"
                 : "=r"(r[0]), "=r"(r[1]), "=r"(r[2]), "=r"(r[3]) : "r"(addr));
}

__device__ __forceinline__ void mma16816(float* c, const uint32_t* a,
                                         const uint32_t* b) {
    asm volatile(
        "mma.sync.aligned.m16n8k16.row.col.f32.bf16.bf16.f32 "
        "{%0,%1,%2,%3}, {%4,%5,%6,%7}, {%8,%9}, {%0,%1,%2,%3};"
        : "+f"(c[0]), "+f"(c[1]), "+f"(c[2]), "+f"(c[3])
        : "r"(a[0]), "r"(a[1]), "r"(a[2]), "r"(a[3]), "r"(b[0]), "r"(b[1]));
}

__device__ __forceinline__ void cpa16(uint32_t saddr, const void* g) {
    asm volatile("cp.async.cg.shared.global [%0], [%1], 16;"
                 :: "r"(saddr), "l"(g));
}
#define CP_COMMIT asm volatile("cp.async.commit_group;")
#define CP_WAIT(n) asm volatile("cp.async.wait_group %0;" :: "n"(n))

__device__ __forceinline__ float ex2(float x) {
    float r;
    asm("ex2.approx.ftz.f32 %0, %1;" : "=f"(r) : "f"(x));
    return r;
}

__device__ __forceinline__ uint32_t packsplit(float a, float b, uint32_t& lo_out) {
    __nv_bfloat16 ha = __float2bfloat16_rn(a);
    __nv_bfloat16 hb = __float2bfloat16_rn(b);
    __nv_bfloat162 hp; hp.x = ha; hp.y = hb;
    __nv_bfloat162 lp = __floats2bfloat162_rn(a - __bfloat162float(ha),
                                              b - __bfloat162float(hb));
    lo_out = reinterpret_cast<uint32_t&>(lp);
    return reinterpret_cast<uint32_t&>(hp);
}

// ---------------------------------------------------------------------------
// fp32 -> (bf16 hi, bf16 lo) split pre-pass for GEMM inputs.
// ---------------------------------------------------------------------------
__global__ __launch_bounds__(256) void cvt_hilo(const float4* __restrict__ in,
                                                int which, int n4) {
    int i = blockIdx.x * blockDim.x + threadIdx.x;
    if (i >= n4) return;
    uint2* hi; uint2* lo;
    if (which == 0)      { hi = (uint2*)g_xhi;  lo = (uint2*)g_xlo;  }
    else if (which == 1) { hi = (uint2*)g_wqhi; lo = (uint2*)g_wqlo; }
    else                 { hi = (uint2*)g_wphi; lo = (uint2*)g_wplo; }
    float4 v = in[i];
    uint2 H, L;
    H.x = packsplit(v.x, v.y, L.x);
    H.y = packsplit(v.z, v.w, L.y);
    hi[i] = H;
    lo[i] = L;
}

// ---------------------------------------------------------------------------
// bf16x3 mma.sync GEMM. CTA 128x128, 8 warps (64x32 each), K-chunk 16,
// 4-stage cp.async pipeline, ONE __syncthreads per chunk (96KB smem,
// 2 CTAs/SM).  mode 0: split-write q/k/v (q pre-scaled); mode 1: +bias->out.
// ---------------------------------------------------------------------------
#define KC    16
#define PITCH 48                       // 32B data + 16B pad, ldsm conflict-free
#define REGB  (128 * PITCH)            // 6144
#define BUFB  (4 * REGB)               // 24576 per stage
#define NSTAGE 4
#define GEMM_SMEM (NSTAGE * BUFB)      // 98304

__global__ __launch_bounds__(256, 2) void gemm_mma(int mode,
                                                   const float* __restrict__ bias,
                                                   float* __restrict__ out) {
    extern __shared__ char smem[];
    const uint32_t sb = s2u(smem);
    const int tid = threadIdx.x;
    const int m0 = blockIdx.y * 128;
    const int o0 = blockIdx.x * 128;

    const __nv_bfloat16* Ahi = ((mode == 0) ? g_xhi  : g_aohi) + (size_t)m0 * Cdim;
    const __nv_bfloat16* Alo = ((mode == 0) ? g_xlo  : g_aolo) + (size_t)m0 * Cdim;
    const __nv_bfloat16* Bhi = ((mode == 0) ? g_wqhi : g_wphi) + (size_t)o0 * Cdim;
    const __nv_bfloat16* Blo = ((mode == 0) ? g_wqlo : g_wplo) + (size_t)o0 * Cdim;
    const __nv_bfloat16* srcs[4] = {Ahi, Alo, Bhi, Blo};

    // per chunk: 4 regions x 128 rows x 32B = 1024 cp.async16 / 256 thr = 4 ea
    auto issue = [&](int c, int stage) {
        uint32_t s0 = sb + stage * BUFB;
        const int ko = c * KC;
#pragma unroll
        for (int j = 0; j < 4; j++) {
            int idx = j * 256 + tid;      // 0..1023
            int mt  = idx >> 8;
            int r   = (idx >> 1) & 127;
            int c8  = idx & 1;
            cpa16(s0 + mt * REGB + r * PITCH + c8 * 16,
                  srcs[mt] + r * Cdim + ko + c8 * 8);
        }
    };

    const int wid = tid >> 5, lane = tid & 31;
    const int wm = wid >> 2;
    const int wn = wid & 3;

    const int a_row  = wm * 64 + (lane & 15);
    const int a_colb = (lane >> 4) * 16;
    const int b_row  = wn * 32 + ((lane >> 4) << 3) + (lane & 7);
    const int b_colb = ((lane >> 3) & 1) * 16;

    float acc[4][4][4];
#pragma unroll
    for (int i = 0; i < 4; i++)
#pragma unroll
        for (int j = 0; j < 4; j++)
#pragma unroll
            for (int k = 0; k < 4; k++) acc[i][j][k] = 0.0f;

    issue(0, 0); CP_COMMIT;
    issue(1, 1); CP_COMMIT;
    issue(2, 2); CP_COMMIT;

    const int NCH = Cdim / KC;   // 64
    for (int c = 0; c < NCH; c++) {
        if (c + 2 < NCH)      { CP_WAIT(2); }
        else if (c + 1 < NCH) { CP_WAIT(1); }
        else                  { CP_WAIT(0); }
        __syncthreads();

        const uint32_t base = sb + (c & 3) * BUFB;
        uint32_t Ah[4][4], Al[4][4], Bh[2][4], Bl[2][4];
#pragma unroll
        for (int mb = 0; mb < 4; mb++) {
            uint32_t ra = base + (a_row + mb * 16) * PITCH + a_colb;
            ldsm4(Ah[mb], ra);
            ldsm4(Al[mb], ra + REGB);
        }
#pragma unroll
        for (int nbp = 0; nbp < 2; nbp++) {
            uint32_t rb = base + 2 * REGB + (b_row + nbp * 16) * PITCH + b_colb;
            ldsm4(Bh[nbp], rb);
            ldsm4(Bl[nbp], rb + REGB);
        }
#pragma unroll
        for (int mb = 0; mb < 4; mb++)
#pragma unroll
            for (int nb = 0; nb < 4; nb++) {
                const uint32_t* bh = &Bh[nb >> 1][(nb & 1) * 2];
                const uint32_t* bl = &Bl[nb >> 1][(nb & 1) * 2];
                mma16816(acc[mb][nb], Ah[mb], bh);
                mma16816(acc[mb][nb], Ah[mb], bl);
                mma16816(acc[mb][nb], Al[mb], bh);
            }
        // refill stage (c+3)&3 == (c-1)&3: last read finished before the
        // barrier at the top of this chunk -> no trailing barrier needed.
        if (c + 3 < NCH) { issue(c + 3, (c + 3) & 3); CP_COMMIT; }
    }

    const int erow = m0 + wm * 64 + (lane >> 2);
    const int ecol = o0 + wn * 32 + (lane & 3) * 2;
    if (mode == 0) {
        const int which = o0 >> 10;
        __nv_bfloat16 *hip, *lop;
        float sc;
        const float qs = 0.125f * 1.44269504088896340736f;
        if (which == 0)      { hip = g_qhi; lop = g_qlo; sc = qs; }
        else if (which == 1) { hip = g_khi; lop = g_klo; sc = 1.0f; }
        else                 { hip = g_vhi; lop = g_vlo; sc = 1.0f; }
#pragma unroll
        for (int mb = 0; mb < 4; mb++) {
            const int m = erow + mb * 16;
            const int bb = m >> 10, n = m & 1023;
#pragma unroll
            for (int nb = 0; nb < 4; nb++) {
                const int o = ecol + nb * 8;
                const int h = (o & 1023) >> 6;
                const int d = o & 63;
                size_t base = ((size_t)(bb * Hn + h) * Nseq + n) * Dh + d;
                uint32_t L0, L1;
                uint32_t H0 = packsplit(acc[mb][nb][0] * sc, acc[mb][nb][1] * sc, L0);
                uint32_t H1 = packsplit(acc[mb][nb][2] * sc, acc[mb][nb][3] * sc, L1);
                *(uint32_t*)(hip + base)            = H0;
                *(uint32_t*)(lop + base)            = L0;
                *(uint32_t*)(hip + base + 8 * Dh)   = H1;
                *(uint32_t*)(lop + base + 8 * Dh)   = L1;
            }
        }
    } else {
#pragma unroll
        for (int mb = 0; mb < 4; mb++) {
            const int m = erow + mb * 16;
#pragma unroll
            for (int nb = 0; nb < 4; nb++) {
                const int o = ecol + nb * 8;
                const float2 bv = *(const float2*)(bias + o);
                float* dst = out + (size_t)m * Cdim + o;
                *(float2*)dst = make_float2(acc[mb][nb][0] + bv.x,
                                            acc[mb][nb][1] + bv.y);
                *(float2*)(dst + 8 * Cdim) = make_float2(acc[mb][nb][2] + bv.x,
                                                         acc[mb][nb][3] + bv.y);
            }
        }
    }
}

// ---------------------------------------------------------------------------
// Flash attention via mma.sync bf16x3.
// CTA: 128 Q rows x one (b,h). 8 warps, 16 Q rows each. KV in 64-row tiles,
// 2-stage cp.async (108KB smem -> 2 CTAs/SM). P split in-register.
// ---------------------------------------------------------------------------
#define APITCH 144                       // 64 bf16 + 8 pad
#define AQREG  (128 * APITCH)            // 18432, Q hi/lo (128 rows)
#define AKREG  (64 * APITCH)             // 9216 per KV matrix (64 rows)
#define AKV0   (2 * AQREG)               // 36864
#define ASTAGE (4 * AKREG)               // Kh,Kl,Vh,Vl = 36864
#define ATTN_SMEM (2 * AQREG + 2 * ASTAGE)  // 110592

__global__ __launch_bounds__(256, 2) void attn_mma() {
    extern __shared__ char smem[];
    const uint32_t sb = s2u(smem);
    const int tid = threadIdx.x;
    const int w = tid >> 5, lane = tid & 31;
    const int bh = blockIdx.x;           // 0..127
    const int qb = blockIdx.y;           // 0..7

    const size_t hoff = (size_t)bh * (Nseq * Dh);
    const __nv_bfloat16* qh = g_qhi + hoff + (size_t)qb * 128 * Dh;
    const __nv_bfloat16* ql = g_qlo + hoff + (size_t)qb * 128 * Dh;

    auto loadQ = [&]() {
#pragma unroll
        for (int j = 0; j < 8; j++) {
            int idx = j * 256 + tid;          // 0..2047
            int mt  = idx >> 10;              // 0=hi 1=lo
            int r   = (idx >> 3) & 127;
            int c8  = idx & 7;
            const __nv_bfloat16* src = mt ? ql : qh;
            cpa16(sb + mt * AQREG + r * APITCH + c8 * 16, src + r * Dh + c8 * 8);
        }
    };
    auto loadKV = [&](int kb, int st) {     // kb: 64-row block id 0..15
        const size_t koff = hoff + (size_t)kb * 64 * Dh;
        const __nv_bfloat16* srcs[4] = {g_khi + koff, g_klo + koff,
                                        g_vhi + koff, g_vlo + koff};
        uint32_t base = sb + AKV0 + st * ASTAGE;
#pragma unroll
        for (int j = 0; j < 8; j++) {
            int idx = j * 256 + tid;          // 0..2047
            int mt  = idx >> 9;               // matrix 0..3
            int r   = (idx >> 3) & 63;
            int c8  = idx & 7;
            cpa16(base + mt * AKREG + r * APITCH + c8 * 16,
                  srcs[mt] + r * Dh + c8 * 8);
        }
    };

    loadQ();          CP_COMMIT;
    loadKV(0, 0);     CP_COMMIT;
    loadKV(1, 1);     CP_COMMIT;

    const int a_rowb = (w * 16 + (lane & 15)) * APITCH + (lane >> 4) * 16;
    const int k_rowi = ((lane >> 4) << 3) + (lane & 7);      // + ng*16
    const int k_colb = ((lane >> 3) & 1) * 16;               // + kc*32
    const int v_rowi = (lane & 7) + ((lane >> 3) & 1) * 8;   // + kc2*16
    const int v_colb = (lane >> 4) * 16;                     // + dg*32

    CP_WAIT(2);       // Q resident
    __syncthreads();

    uint32_t QAh[4][4];
#pragma unroll
    for (int kc = 0; kc < 4; kc++)
        ldsm4(QAh[kc], sb + a_rowb + kc * 32);

    float O[8][4];
#pragma unroll
    for (int i = 0; i < 8; i++)
#pragma unroll
        for (int j = 0; j < 4; j++) O[i][j] = 0.0f;
    float m0 = -1e30f, m1 = -1e30f;
    float l0 = 0.0f, l1 = 0.0f;

    for (int kb = 0; kb < 16; kb++) {
        if (kb + 1 < 16) { CP_WAIT(1); } else { CP_WAIT(0); }
        __syncthreads();
        const uint32_t kbase = sb + AKV0 + (kb & 1) * ASTAGE;

        // Q-lo frags from smem (saves 16 persistent regs)
        uint32_t QAl[4][4];
#pragma unroll
        for (int kc = 0; kc < 4; kc++)
            ldsm4(QAl[kc], sb + AQREG + a_rowb + kc * 32);

        // ----- S = Q K^T (3 passes), 64 cols = 4 n-groups ------------------
        float S[8][4];
#pragma unroll
        for (int i = 0; i < 8; i++)
#pragma unroll
            for (int j = 0; j < 4; j++) S[i][j] = 0.0f;

#pragma unroll
        for (int ng = 0; ng < 4; ng++) {
#pragma unroll
            for (int kc = 0; kc < 4; kc++) {
                uint32_t kbh[4], kbl[4];
                uint32_t rb = kbase + (ng * 16 + k_rowi) * APITCH
                            + k_colb + kc * 32;
                ldsm4(kbh, rb);
                ldsm4(kbl, rb + AKREG);
#pragma unroll
                for (int half = 0; half < 2; half++) {
                    float* s = S[ng * 2 + half];
                    mma16816(s, QAh[kc], &kbh[half * 2]);
                    mma16816(s, QAh[kc], &kbl[half * 2]);
                    mma16816(s, QAl[kc], &kbh[half * 2]);
                }
            }
        }

        // ----- online softmax ---------------------------------------------
        float rm0 = -1e30f, rm1 = -1e30f;
#pragma unroll
        for (int i = 0; i < 8; i++) {
            rm0 = fmaxf(rm0, fmaxf(S[i][0], S[i][1]));
            rm1 = fmaxf(rm1, fmaxf(S[i][2], S[i][3]));
        }
        rm0 = fmaxf(rm0, __shfl_xor_sync(0xffffffffu, rm0, 1));
        rm0 = fmaxf(rm0, __shfl_xor_sync(0xffffffffu, rm0, 2));
        rm1 = fmaxf(rm1, __shfl_xor_sync(0xffffffffu, rm1, 1));
        rm1 = fmaxf(rm1, __shfl_xor_sync(0xffffffffu, rm1, 2));

        float mn0 = fmaxf(m0, rm0), mn1 = fmaxf(m1, rm1);
        float al0 = ex2(m0 - mn0),  al1 = ex2(m1 - mn1);
        m0 = mn0; m1 = mn1;
        l0 *= al0; l1 *= al1;
#pragma unroll
        for (int i = 0; i < 8; i++) {
            O[i][0] *= al0; O[i][1] *= al0;
            O[i][2] *= al1; O[i][3] *= al1;
        }
        float ps0 = 0.0f, ps1 = 0.0f;
#pragma unroll
        for (int i = 0; i < 8; i++) {
            S[i][0] = ex2(S[i][0] - mn0);
            S[i][1] = ex2(S[i][1] - mn0);
            S[i][2] = ex2(S[i][2] - mn1);
            S[i][3] = ex2(S[i][3] - mn1);
            ps0 += S[i][0] + S[i][1];
            ps1 += S[i][2] + S[i][3];
        }
        l0 += ps0; l1 += ps1;

        // ----- O += P V (3 passes), 64 KV rows = 4 k-chunks ----------------
#pragma unroll
        for (int kc2 = 0; kc2 < 4; kc2++) {
            uint32_t pah[4], pal[4];
            pah[0] = packsplit(S[2 * kc2][0],     S[2 * kc2][1],     pal[0]);
            pah[1] = packsplit(S[2 * kc2][2],     S[2 * kc2][3],     pal[1]);
            pah[2] = packsplit(S[2 * kc2 + 1][0], S[2 * kc2 + 1][1], pal[2]);
            pah[3] = packsplit(S[2 * kc2 + 1][2], S[2 * kc2 + 1][3], pal[3]);
#pragma unroll
            for (int dg = 0; dg < 4; dg++) {
                uint32_t vbh[4], vbl[4];
                uint32_t rv = kbase + 2 * AKREG
                            + (kc2 * 16 + v_rowi) * APITCH + v_colb + dg * 32;
                ldsm4t(vbh, rv);
                ldsm4t(vbl, rv + AKREG);
#pragma unroll
                for (int half = 0; half < 2; half++) {
                    float* o = O[dg * 2 + half];
                    mma16816(o, pah, &vbh[half * 2]);
                    mma16816(o, pah, &vbl[half * 2]);
                    mma16816(o, pal, &vbh[half * 2]);
                }
            }
        }

        __syncthreads();
        if (kb + 2 < 16) { loadKV(kb + 2, kb & 1); CP_COMMIT; }
    }

    // ----- finalize + write bf16 hi/lo for proj GEMM -----------------------
    l0 += __shfl_xor_sync(0xffffffffu, l0, 1);
    l0 += __shfl_xor_sync(0xffffffffu, l0, 2);
    l1 += __shfl_xor_sync(0xffffffffu, l1, 1);
    l1 += __shfl_xor_sync(0xffffffffu, l1, 2);
    const float inv0 = 1.0f / l0, inv1 = 1.0f / l1;

    const int b = bh >> 4, h = bh & 15;
    const int n0 = qb * 128 + w * 16 + (lane >> 2);
#pragma unroll
    for (int nb = 0; nb < 8; nb++) {
        const int d = nb * 8 + (lane & 3) * 2;
        size_t base0 = ((size_t)(b * Nseq + n0) * Cdim) + h * Dh + d;
        size_t base1 = base0 + (size_t)8 * Cdim;
        uint32_t L0, L1;
        uint32_t H0 = packsplit(O[nb][0] * inv0, O[nb][1] * inv0, L0);
        uint32_t H1 = packsplit(O[nb][2] * inv1, O[nb][3] * inv1, L1);
        *(uint32_t*)(g_aohi + base0) = H0;
        *(uint32_t*)(g_aolo + base0) = L0;
        *(uint32_t*)(g_aohi + base1) = H1;
        *(uint32_t*)(g_aolo + base1) = L1;
    }
}

// ---------------------------------------------------------------------------
extern "C" void kernel_launch(void* const* d_in, const int* in_sizes, int n_in,
                              void* d_out, int out_size) {
    const float* x      = (const float*)d_in[0];   // [8,1024,1024]
    const float* w_qkv  = (const float*)d_in[1];   // [3072,1024]
    const float* w_proj = (const float*)d_in[2];   // [1024,1024]
    const float* b_proj = (const float*)d_in[3];   // [1024]
    float* out = (float*)d_out;

    cudaFuncSetAttribute(gemm_mma,
                         cudaFuncAttributeMaxDynamicSharedMemorySize, GEMM_SMEM);
    cudaFuncSetAttribute(attn_mma,
                         cudaFuncAttributeMaxDynamicSharedMemorySize, ATTN_SMEM);

    {
        int n4 = (Mrows * Cdim) / 4;
        cvt_hilo<<<(n4 + 255) / 256, 256>>>((const float4*)x, 0, n4);
    }
    {
        int n4 = (OQKV * Cdim) / 4;
        cvt_hilo<<<(n4 + 255) / 256, 256>>>((const float4*)w_qkv, 1, n4);
    }
    {
        int n4 = (Cdim * Cdim) / 4;
        cvt_hilo<<<(n4 + 255) / 256, 256>>>((const float4*)w_proj, 2, n4);
    }

    dim3 g1(OQKV / 128, Mrows / 128);              // (24, 64)
    gemm_mma<<<g1, 256, GEMM_SMEM>>>(0, nullptr, nullptr);

    dim3 g2(Bsz * Hn, Nseq / 128);                 // (128, 8)
    attn_mma<<<g2, 256, ATTN_SMEM>>>();

    dim3 g3(Cdim / 128, Mrows / 128);              // (8, 64)
    gemm_mma<<<g3, 256, GEMM_SMEM>>>(1, b_proj, out);
}